// round 4
// baseline (speedup 1.0000x reference)
#include <cuda_runtime.h>
#include <cstddef>

#define N_NODESC 100000
#define N_EDGESC 1600000
#define NFEAT 7
#define HID 128
#define NCLASS 5
#define NGRAPHS 8

// ---------------- scratch (device globals; no allocation allowed) ----------
__device__ __align__(16) float g_agg[N_NODESC * HID];
__device__ __align__(16) float g_h0[N_NODESC * HID];
__device__ __align__(16) float g_h1[N_NODESC * HID];
__device__ float g_pool[NGRAPHS * HID];
__device__ float g_cnt[NGRAPHS];

// vectorized fp32 reduction (sm_90+): one 16B L2 RMW instead of 4 scalar REDs
__device__ __forceinline__ void red_add_v4(float* addr, float4 v) {
    asm volatile("red.global.add.v4.f32 [%0], {%1, %2, %3, %4};"
                 :: "l"(addr), "f"(v.x), "f"(v.y), "f"(v.z), "f"(v.w)
                 : "memory");
}

// ---------------- layer 1 scatter: in = 7, thread per edge ----------------
__global__ void scatter7(const float* __restrict__ x,
                         const int* __restrict__ src,
                         const int* __restrict__ dst,
                         const float* __restrict__ ea,
                         const float* __restrict__ We,
                         const float* __restrict__ be,
                         float* __restrict__ agg) {
    int e = blockIdx.x * blockDim.x + threadIdx.x;
    if (e >= N_EDGESC) return;
    int s = src[e], d = dst[e];
    float a = ea[e];
    float w[NFEAT], bb[NFEAT];
#pragma unroll
    for (int j = 0; j < NFEAT; j++) { w[j] = __ldg(&We[j]); bb[j] = __ldg(&be[j]); }
#pragma unroll
    for (int j = 0; j < NFEAT; j++) {
        float m = fmaxf(fmaf(a, w[j], bb[j]) + __ldg(&x[s * NFEAT + j]), 0.0f);
        atomicAdd(&agg[d * NFEAT + j], m);
    }
}

// ---------------- layer 1 gemm: [N,7] @ [7,128], relu ---------------------
#define GM1 32
__global__ void gemm7(const float* __restrict__ agg, const float* __restrict__ x,
                      const float* __restrict__ W, const float* __restrict__ b,
                      float* __restrict__ out) {
    __shared__ float Ws[NFEAT * HID];
    __shared__ float bs[HID];
    int j = threadIdx.x;  // 128 threads
#pragma unroll
    for (int k = 0; k < NFEAT; k++) Ws[k * HID + j] = W[k * HID + j];
    bs[j] = b[j];
    __syncthreads();
    int row0 = blockIdx.x * GM1;
    for (int r = 0; r < GM1; r++) {
        int row = row0 + r;
        if (row >= N_NODESC) return;
        float a[NFEAT];
#pragma unroll
        for (int k = 0; k < NFEAT; k++)
            a[k] = __ldg(&agg[row * NFEAT + k]) + __ldg(&x[row * NFEAT + k]);
        float acc = bs[j];
#pragma unroll
        for (int k = 0; k < NFEAT; k++) acc = fmaf(a[k], Ws[k * HID + j], acc);
        out[(size_t)row * HID + j] = fmaxf(acc, 0.0f);
    }
}

// ---------------- layers 2,3 scatter: in = 128, warp per edge -------------
__global__ void __launch_bounds__(512)
scatter128(const float* __restrict__ hin,
           const int* __restrict__ src,
           const int* __restrict__ dst,
           const float* __restrict__ ea,
           const float* __restrict__ We,
           const float* __restrict__ be,
           float* __restrict__ agg) {
    int gt = blockIdx.x * blockDim.x + threadIdx.x;
    int e = gt >> 5;
    int lane = gt & 31;
    if (e >= N_EDGESC) return;
    // uniform per-edge scalars (warp-broadcast loads), issued first
    int s = __ldg(&src[e]);
    int d = __ldg(&dst[e]);
    float a = __ldg(&ea[e]);
    // random 512B row gather (L2-resident)
    float4 v = ((const float4*)(hin + (size_t)s * HID))[lane];
    float4 w = __ldg(&((const float4*)We)[lane]);
    float4 bb = __ldg(&((const float4*)be)[lane]);
    float4 m;
    m.x = fmaxf(fmaf(a, w.x, bb.x) + v.x, 0.0f);
    m.y = fmaxf(fmaf(a, w.y, bb.y) + v.y, 0.0f);
    m.z = fmaxf(fmaf(a, w.z, bb.z) + v.z, 0.0f);
    m.w = fmaxf(fmaf(a, w.w, bb.w) + v.w, 0.0f);
    red_add_v4(agg + (size_t)d * HID + lane * 4, m);
}

// ---------------- layers 2,3 gemm: relu((agg + xin) @ W + b) --------------
// BM=64, BN=128 (full), 256 threads, 8x4 register tile per thread.
#define BM 64
#define GEMM_SMEM ((HID * HID + BM * HID + HID) * 4)
__global__ void __launch_bounds__(256, 2)
gemm128(const float* __restrict__ agg, const float* __restrict__ xin,
        const float* __restrict__ W, const float* __restrict__ b,
        float* __restrict__ out) {
    extern __shared__ float smem[];
    float* Ws = smem;                 // [128][128]
    float* As = smem + HID * HID;     // [64][128]
    float* bs = As + BM * HID;        // [128]

    // stage W (64KB) + b once per block
    {
        const float4* Wg = (const float4*)W;
        float4* Ws4 = (float4*)Ws;
        for (int i = threadIdx.x; i < HID * (HID / 4); i += 256) Ws4[i] = Wg[i];
        if (threadIdx.x < HID) bs[threadIdx.x] = b[threadIdx.x];
    }
    __syncthreads();

    int cg = threadIdx.x & 31;   // column group -> j0
    int rg = threadIdx.x >> 5;   // row group  -> r0
    int j0 = cg * 4;
    int r0 = rg * 8;

    int ntiles = (N_NODESC + BM - 1) / BM;
    for (int tile = blockIdx.x; tile < ntiles; tile += gridDim.x) {
        int row0 = tile * BM;
        // stage A tile: agg + xin
        {
            float4* As4 = (float4*)As;
            for (int i = threadIdx.x; i < BM * (HID / 4); i += 256) {
                int r = i >> 5;
                int kq = i & 31;
                int row = row0 + r;
                float4 v = make_float4(0.f, 0.f, 0.f, 0.f);
                if (row < N_NODESC) {
                    float4 ag = ((const float4*)(agg + (size_t)row * HID))[kq];
                    float4 xx = ((const float4*)(xin + (size_t)row * HID))[kq];
                    v = make_float4(ag.x + xx.x, ag.y + xx.y, ag.z + xx.z, ag.w + xx.w);
                }
                As4[i] = v;
            }
        }
        __syncthreads();

        float acc[8][4];
        {
            float4 bv = *(const float4*)&bs[j0];
#pragma unroll
            for (int i = 0; i < 8; i++) {
                acc[i][0] = bv.x; acc[i][1] = bv.y; acc[i][2] = bv.z; acc[i][3] = bv.w;
            }
        }

#pragma unroll 4
        for (int kk = 0; kk < HID; kk += 4) {
            float4 av[8];
#pragma unroll
            for (int i = 0; i < 8; i++)
                av[i] = *(const float4*)&As[(r0 + i) * HID + kk];
#pragma unroll
            for (int q = 0; q < 4; q++) {
                float4 wv = *(const float4*)&Ws[(kk + q) * HID + j0];
#pragma unroll
                for (int i = 0; i < 8; i++) {
                    float aval = (q == 0) ? av[i].x : (q == 1) ? av[i].y
                               : (q == 2) ? av[i].z : av[i].w;
                    acc[i][0] = fmaf(aval, wv.x, acc[i][0]);
                    acc[i][1] = fmaf(aval, wv.y, acc[i][1]);
                    acc[i][2] = fmaf(aval, wv.z, acc[i][2]);
                    acc[i][3] = fmaf(aval, wv.w, acc[i][3]);
                }
            }
        }

#pragma unroll
        for (int i = 0; i < 8; i++) {
            int row = row0 + r0 + i;
            if (row < N_NODESC) {
                float4 o;
                o.x = fmaxf(acc[i][0], 0.0f);
                o.y = fmaxf(acc[i][1], 0.0f);
                o.z = fmaxf(acc[i][2], 0.0f);
                o.w = fmaxf(acc[i][3], 0.0f);
                *(float4*)&out[(size_t)row * HID + j0] = o;
            }
        }
        __syncthreads();
    }
}

// ---------------- mean pool: segment sums over sorted batch ---------------
#define POOL_CHUNK 512
__global__ void pool_kernel(const float* __restrict__ h,
                            const int* __restrict__ batch,
                            float* __restrict__ pool,
                            float* __restrict__ cnt) {
    int j = threadIdx.x;  // 128
    int start = blockIdx.x * POOL_CHUNK;
    if (start >= N_NODESC) return;
    int end = start + POOL_CHUNK;
    if (end > N_NODESC) end = N_NODESC;
    int cur = __ldg(&batch[start]);
    float acc = 0.0f, c = 0.0f;
    for (int i = start; i < end; i++) {
        int bg = __ldg(&batch[i]);
        if (bg != cur) {
            atomicAdd(&pool[cur * HID + j], acc);
            if (j == 0) atomicAdd(&cnt[cur], c);
            acc = 0.0f; c = 0.0f; cur = bg;
        }
        acc += h[(size_t)i * HID + j];
        c += 1.0f;
    }
    atomicAdd(&pool[cur * HID + j], acc);
    if (j == 0) atomicAdd(&cnt[cur], c);
}

// ---------------- final: (pool/cnt) @ Wlin + blin, 8x5 out ----------------
__global__ void final_kernel(const float* __restrict__ pool,
                             const float* __restrict__ cnt,
                             const float* __restrict__ Wlin,
                             const float* __restrict__ blin,
                             float* __restrict__ out) {
    int t = threadIdx.x;
    if (t >= NGRAPHS * NCLASS) return;
    int g = t / NCLASS, c = t % NCLASS;
    float inv = 1.0f / fmaxf(cnt[g], 1.0f);
    float acc = blin[c];
#pragma unroll 8
    for (int k = 0; k < HID; k++)
        acc = fmaf(pool[g * HID + k] * inv, Wlin[k * NCLASS + c], acc);
    out[t] = acc;
}

// ---------------- launch ---------------------------------------------------
extern "C" void kernel_launch(void* const* d_in, const int* in_sizes, int n_in,
                              void* d_out, int out_size) {
    const float* x    = (const float*)d_in[0];
    const int*   ei   = (const int*)d_in[1];
    const float* ea   = (const float*)d_in[2];
    const int*   batch= (const int*)d_in[3];
    const float* We1  = (const float*)d_in[4];
    const float* be1  = (const float*)d_in[5];
    const float* W1   = (const float*)d_in[6];
    const float* b1   = (const float*)d_in[7];
    const float* We2  = (const float*)d_in[8];
    const float* be2  = (const float*)d_in[9];
    const float* W2   = (const float*)d_in[10];
    const float* b2   = (const float*)d_in[11];
    const float* We3  = (const float*)d_in[12];
    const float* be3  = (const float*)d_in[13];
    const float* W3   = (const float*)d_in[14];
    const float* b3   = (const float*)d_in[15];
    const float* Wlin = (const float*)d_in[16];
    const float* blin = (const float*)d_in[17];
    float* out = (float*)d_out;

    const int* src = ei;
    const int* dst = ei + N_EDGESC;

    float *agg, *h0, *h1, *pool, *cnt;
    cudaGetSymbolAddress((void**)&agg, g_agg);
    cudaGetSymbolAddress((void**)&h0, g_h0);
    cudaGetSymbolAddress((void**)&h1, g_h1);
    cudaGetSymbolAddress((void**)&pool, g_pool);
    cudaGetSymbolAddress((void**)&cnt, g_cnt);

    cudaFuncSetAttribute(gemm128, cudaFuncAttributeMaxDynamicSharedMemorySize,
                         GEMM_SMEM);

    const int scat128_blocks = (N_EDGESC * 32 + 511) / 512;

    // ---- layer 1 (in=7) ----
    cudaMemsetAsync(agg, 0, (size_t)N_NODESC * NFEAT * sizeof(float));
    scatter7<<<(N_EDGESC + 255) / 256, 256>>>(x, src, dst, ea, We1, be1, agg);
    gemm7<<<(N_NODESC + GM1 - 1) / GM1, 128>>>(agg, x, W1, b1, h0);

    // ---- layer 2 ----
    cudaMemsetAsync(agg, 0, (size_t)N_NODESC * HID * sizeof(float));
    scatter128<<<scat128_blocks, 512>>>(h0, src, dst, ea, We2, be2, agg);
    gemm128<<<296, 256, GEMM_SMEM>>>(agg, h0, W2, b2, h1);

    // ---- layer 3 ----
    cudaMemsetAsync(agg, 0, (size_t)N_NODESC * HID * sizeof(float));
    scatter128<<<scat128_blocks, 512>>>(h1, src, dst, ea, We3, be3, agg);
    gemm128<<<296, 256, GEMM_SMEM>>>(agg, h1, W3, b3, h0);

    // ---- mean pool + classifier ----
    cudaMemsetAsync(pool, 0, NGRAPHS * HID * sizeof(float));
    cudaMemsetAsync(cnt, 0, NGRAPHS * sizeof(float));
    pool_kernel<<<(N_NODESC + POOL_CHUNK - 1) / POOL_CHUNK, 128>>>(h0, batch, pool, cnt);
    final_kernel<<<1, 64>>>(pool, cnt, Wlin, blin, out);
}

// round 8
// speedup vs baseline: 1.4954x; 1.4954x over previous
#include <cuda_runtime.h>
#include <cstddef>

#define N_NODESC 100000
#define N_EDGESC 1600000
#define NFEAT 7
#define HID 128
#define NCLASS 5
#define NGRAPHS 8

// ---------------- scratch (device globals; no allocation allowed) ----------
__device__ __align__(16) float g_agg[N_NODESC * HID];
__device__ __align__(16) float g_h0[N_NODESC * HID];
__device__ __align__(16) float g_h1[N_NODESC * HID];
__device__ float g_pool[NGRAPHS * HID];
__device__ float g_cnt[NGRAPHS];
// CSR-by-destination scratch
__device__ int g_deg[N_NODESC];
__device__ int g_off[N_NODESC + 1];
__device__ int g_cur[N_NODESC];
__device__ int g_bsum[128];
__device__ int g_perm[N_EDGESC];

// ================= CSR build ===============================================
// 1) histogram of destination degrees
__global__ void hist_kernel(const int* __restrict__ dst, int* __restrict__ deg) {
    int e = blockIdx.x * blockDim.x + threadIdx.x;
    if (e < N_EDGESC) atomicAdd(&deg[dst[e]], 1);
}

// 2) exclusive scan of deg -> off  (3-phase: local, block-sums, add)
#define SCAN_T 256
#define SCAN_E 1024   // elems per block (4 per thread)
#define SCAN_NB ((N_NODESC + SCAN_E - 1) / SCAN_E)   // 98

__global__ void scan_local(const int* __restrict__ deg, int* __restrict__ off,
                           int* __restrict__ bsum) {
    __shared__ int tsum[SCAN_T];
    int b = blockIdx.x, t = threadIdx.x;
    int base = b * SCAN_E + t * 4;
    int v[4], ex[4];
    int run = 0;
#pragma unroll
    for (int j = 0; j < 4; j++) {
        int idx = base + j;
        v[j] = (idx < N_NODESC) ? deg[idx] : 0;
        ex[j] = run;
        run += v[j];
    }
    tsum[t] = run;
    __syncthreads();
    // inclusive Hillis-Steele scan over thread sums
    for (int ofs = 1; ofs < SCAN_T; ofs <<= 1) {
        int val = (t >= ofs) ? tsum[t - ofs] : 0;
        __syncthreads();
        tsum[t] += val;
        __syncthreads();
    }
    int texc = tsum[t] - run;  // exclusive prefix for this thread
#pragma unroll
    for (int j = 0; j < 4; j++) {
        int idx = base + j;
        if (idx < N_NODESC) off[idx] = texc + ex[j];
    }
    if (t == SCAN_T - 1) bsum[b] = tsum[t];
}

__global__ void scan_sums(int* __restrict__ bsum) {
    if (threadIdx.x == 0) {
        int run = 0;
        for (int b = 0; b < SCAN_NB; b++) {
            int t = bsum[b];
            bsum[b] = run;
            run += t;
        }
    }
}

__global__ void scan_add(int* __restrict__ off, const int* __restrict__ bsum) {
    int b = blockIdx.x, t = threadIdx.x;
    int add = bsum[b];
    int base = b * SCAN_E + t * 4;
#pragma unroll
    for (int j = 0; j < 4; j++) {
        int idx = base + j;
        if (idx < N_NODESC) off[idx] += add;
    }
    if (b == 0 && t == 0) off[N_NODESC] = N_EDGESC;
}

// 3) fill permutation (edge ids grouped by destination)
__global__ void fill_kernel(const int* __restrict__ dst, int* __restrict__ cur,
                            int* __restrict__ perm) {
    int e = blockIdx.x * blockDim.x + threadIdx.x;
    if (e < N_EDGESC) {
        int p = atomicAdd(&cur[dst[e]], 1);
        perm[p] = e;
    }
}

// ================= layer 1: in = 7, gather by destination ==================
__global__ void __launch_bounds__(256)
gather7(const float* __restrict__ x, const int* __restrict__ src,
        const float* __restrict__ ea, const int* __restrict__ perm,
        const int* __restrict__ off, const float* __restrict__ We,
        const float* __restrict__ be, float* __restrict__ agg7) {
    int n = (blockIdx.x * blockDim.x + threadIdx.x) >> 5;
    int lane = threadIdx.x & 31;
    if (n >= N_NODESC) return;
    float w[NFEAT], bb[NFEAT];
#pragma unroll
    for (int j = 0; j < NFEAT; j++) { w[j] = __ldg(&We[j]); bb[j] = __ldg(&be[j]); }
    int i0 = __ldg(&off[n]), i1 = __ldg(&off[n + 1]);
    float acc[NFEAT];
#pragma unroll
    for (int j = 0; j < NFEAT; j++) acc[j] = 0.0f;
    for (int i = i0 + lane; i < i1; i += 32) {
        int e = __ldg(&perm[i]);
        int s = __ldg(&src[e]);
        float a = __ldg(&ea[e]);
#pragma unroll
        for (int j = 0; j < NFEAT; j++)
            acc[j] += fmaxf(fmaf(a, w[j], bb[j]) + __ldg(&x[s * NFEAT + j]), 0.0f);
    }
#pragma unroll
    for (int o = 16; o > 0; o >>= 1)
#pragma unroll
        for (int j = 0; j < NFEAT; j++)
            acc[j] += __shfl_down_sync(0xffffffffu, acc[j], o);
    if (lane == 0) {
#pragma unroll
        for (int j = 0; j < NFEAT; j++) agg7[n * NFEAT + j] = acc[j];
    }
}

// ---------------- layer 1 gemm: [N,7] @ [7,128], relu ---------------------
#define GM1 32
__global__ void gemm7(const float* __restrict__ agg, const float* __restrict__ x,
                      const float* __restrict__ W, const float* __restrict__ b,
                      float* __restrict__ out) {
    __shared__ float Ws[NFEAT * HID];
    __shared__ float bs[HID];
    int j = threadIdx.x;  // 128 threads
#pragma unroll
    for (int k = 0; k < NFEAT; k++) Ws[k * HID + j] = W[k * HID + j];
    bs[j] = b[j];
    __syncthreads();
    int row0 = blockIdx.x * GM1;
    for (int r = 0; r < GM1; r++) {
        int row = row0 + r;
        if (row >= N_NODESC) return;
        float a[NFEAT];
#pragma unroll
        for (int k = 0; k < NFEAT; k++)
            a[k] = __ldg(&agg[row * NFEAT + k]) + __ldg(&x[row * NFEAT + k]);
        float acc = bs[j];
#pragma unroll
        for (int k = 0; k < NFEAT; k++) acc = fmaf(a[k], Ws[k * HID + j], acc);
        out[(size_t)row * HID + j] = fmaxf(acc, 0.0f);
    }
}

// ================= layers 2,3: gather-aggregate, warp per node =============
__global__ void __launch_bounds__(256)
gather128(const float* __restrict__ hin, const int* __restrict__ src,
          const float* __restrict__ ea, const int* __restrict__ perm,
          const int* __restrict__ off, const float* __restrict__ We,
          const float* __restrict__ be, float* __restrict__ agg) {
    int n = (blockIdx.x * blockDim.x + threadIdx.x) >> 5;
    int lane = threadIdx.x & 31;
    if (n >= N_NODESC) return;
    float4 w = __ldg(&((const float4*)We)[lane]);
    float4 bb = __ldg(&((const float4*)be)[lane]);
    int i = __ldg(&off[n]);
    int end = __ldg(&off[n + 1]);
    const float4* h4 = (const float4*)hin;
    float4 acc = make_float4(0.f, 0.f, 0.f, 0.f);
    // 2-edge software pipeline for MLP
    for (; i + 2 <= end; i += 2) {
        int e0 = __ldg(&perm[i]);
        int e1 = __ldg(&perm[i + 1]);
        int s0 = __ldg(&src[e0]);
        int s1 = __ldg(&src[e1]);
        float a0 = __ldg(&ea[e0]);
        float a1 = __ldg(&ea[e1]);
        float4 v0 = h4[(size_t)s0 * (HID / 4) + lane];
        float4 v1 = h4[(size_t)s1 * (HID / 4) + lane];
        acc.x += fmaxf(fmaf(a0, w.x, bb.x) + v0.x, 0.f);
        acc.y += fmaxf(fmaf(a0, w.y, bb.y) + v0.y, 0.f);
        acc.z += fmaxf(fmaf(a0, w.z, bb.z) + v0.z, 0.f);
        acc.w += fmaxf(fmaf(a0, w.w, bb.w) + v0.w, 0.f);
        acc.x += fmaxf(fmaf(a1, w.x, bb.x) + v1.x, 0.f);
        acc.y += fmaxf(fmaf(a1, w.y, bb.y) + v1.y, 0.f);
        acc.z += fmaxf(fmaf(a1, w.z, bb.z) + v1.z, 0.f);
        acc.w += fmaxf(fmaf(a1, w.w, bb.w) + v1.w, 0.f);
    }
    if (i < end) {
        int e0 = __ldg(&perm[i]);
        int s0 = __ldg(&src[e0]);
        float a0 = __ldg(&ea[e0]);
        float4 v0 = h4[(size_t)s0 * (HID / 4) + lane];
        acc.x += fmaxf(fmaf(a0, w.x, bb.x) + v0.x, 0.f);
        acc.y += fmaxf(fmaf(a0, w.y, bb.y) + v0.y, 0.f);
        acc.z += fmaxf(fmaf(a0, w.z, bb.z) + v0.z, 0.f);
        acc.w += fmaxf(fmaf(a0, w.w, bb.w) + v0.w, 0.f);
    }
    ((float4*)agg)[(size_t)n * (HID / 4) + lane] = acc;
}

// ---------------- layers 2,3 gemm: relu((agg + xin) @ W + b) --------------
#define BM 64
#define GEMM_SMEM ((HID * HID + BM * HID + HID) * 4)
__global__ void __launch_bounds__(256, 2)
gemm128(const float* __restrict__ agg, const float* __restrict__ xin,
        const float* __restrict__ W, const float* __restrict__ b,
        float* __restrict__ out) {
    extern __shared__ float smem[];
    float* Ws = smem;                 // [128][128]
    float* As = smem + HID * HID;     // [64][128]
    float* bs = As + BM * HID;        // [128]

    {
        const float4* Wg = (const float4*)W;
        float4* Ws4 = (float4*)Ws;
        for (int i = threadIdx.x; i < HID * (HID / 4); i += 256) Ws4[i] = Wg[i];
        if (threadIdx.x < HID) bs[threadIdx.x] = b[threadIdx.x];
    }
    __syncthreads();

    int cg = threadIdx.x & 31;
    int rg = threadIdx.x >> 5;
    int j0 = cg * 4;
    int r0 = rg * 8;

    int ntiles = (N_NODESC + BM - 1) / BM;
    for (int tile = blockIdx.x; tile < ntiles; tile += gridDim.x) {
        int row0 = tile * BM;
        {
            float4* As4 = (float4*)As;
            for (int i = threadIdx.x; i < BM * (HID / 4); i += 256) {
                int r = i >> 5;
                int kq = i & 31;
                int row = row0 + r;
                float4 v = make_float4(0.f, 0.f, 0.f, 0.f);
                if (row < N_NODESC) {
                    float4 ag = ((const float4*)(agg + (size_t)row * HID))[kq];
                    float4 xx = ((const float4*)(xin + (size_t)row * HID))[kq];
                    v = make_float4(ag.x + xx.x, ag.y + xx.y, ag.z + xx.z, ag.w + xx.w);
                }
                As4[i] = v;
            }
        }
        __syncthreads();

        float acc[8][4];
        {
            float4 bv = *(const float4*)&bs[j0];
#pragma unroll
            for (int i = 0; i < 8; i++) {
                acc[i][0] = bv.x; acc[i][1] = bv.y; acc[i][2] = bv.z; acc[i][3] = bv.w;
            }
        }

#pragma unroll 4
        for (int kk = 0; kk < HID; kk += 4) {
            float4 av[8];
#pragma unroll
            for (int i = 0; i < 8; i++)
                av[i] = *(const float4*)&As[(r0 + i) * HID + kk];
#pragma unroll
            for (int q = 0; q < 4; q++) {
                float4 wv = *(const float4*)&Ws[(kk + q) * HID + j0];
#pragma unroll
                for (int i = 0; i < 8; i++) {
                    float aval = (q == 0) ? av[i].x : (q == 1) ? av[i].y
                               : (q == 2) ? av[i].z : av[i].w;
                    acc[i][0] = fmaf(aval, wv.x, acc[i][0]);
                    acc[i][1] = fmaf(aval, wv.y, acc[i][1]);
                    acc[i][2] = fmaf(aval, wv.z, acc[i][2]);
                    acc[i][3] = fmaf(aval, wv.w, acc[i][3]);
                }
            }
        }

#pragma unroll
        for (int i = 0; i < 8; i++) {
            int row = row0 + r0 + i;
            if (row < N_NODESC) {
                float4 o;
                o.x = fmaxf(acc[i][0], 0.0f);
                o.y = fmaxf(acc[i][1], 0.0f);
                o.z = fmaxf(acc[i][2], 0.0f);
                o.w = fmaxf(acc[i][3], 0.0f);
                *(float4*)&out[(size_t)row * HID + j0] = o;
            }
        }
        __syncthreads();
    }
}

// ---------------- mean pool: segment sums over sorted batch ---------------
#define POOL_CHUNK 512
__global__ void pool_kernel(const float* __restrict__ h,
                            const int* __restrict__ batch,
                            float* __restrict__ pool,
                            float* __restrict__ cnt) {
    int j = threadIdx.x;  // 128
    int start = blockIdx.x * POOL_CHUNK;
    if (start >= N_NODESC) return;
    int end = start + POOL_CHUNK;
    if (end > N_NODESC) end = N_NODESC;
    int cur = __ldg(&batch[start]);
    float acc = 0.0f, c = 0.0f;
    for (int i = start; i < end; i++) {
        int bg = __ldg(&batch[i]);
        if (bg != cur) {
            atomicAdd(&pool[cur * HID + j], acc);
            if (j == 0) atomicAdd(&cnt[cur], c);
            acc = 0.0f; c = 0.0f; cur = bg;
        }
        acc += h[(size_t)i * HID + j];
        c += 1.0f;
    }
    atomicAdd(&pool[cur * HID + j], acc);
    if (j == 0) atomicAdd(&cnt[cur], c);
}

// ---------------- final: (pool/cnt) @ Wlin + blin, 8x5 out ----------------
__global__ void final_kernel(const float* __restrict__ pool,
                             const float* __restrict__ cnt,
                             const float* __restrict__ Wlin,
                             const float* __restrict__ blin,
                             float* __restrict__ out) {
    int t = threadIdx.x;
    if (t >= NGRAPHS * NCLASS) return;
    int g = t / NCLASS, c = t % NCLASS;
    float inv = 1.0f / fmaxf(cnt[g], 1.0f);
    float acc = blin[c];
#pragma unroll 8
    for (int k = 0; k < HID; k++)
        acc = fmaf(pool[g * HID + k] * inv, Wlin[k * NCLASS + c], acc);
    out[t] = acc;
}

// ---------------- launch ---------------------------------------------------
extern "C" void kernel_launch(void* const* d_in, const int* in_sizes, int n_in,
                              void* d_out, int out_size) {
    const float* x    = (const float*)d_in[0];
    const int*   ei   = (const int*)d_in[1];
    const float* ea   = (const float*)d_in[2];
    const int*   batch= (const int*)d_in[3];
    const float* We1  = (const float*)d_in[4];
    const float* be1  = (const float*)d_in[5];
    const float* W1   = (const float*)d_in[6];
    const float* b1   = (const float*)d_in[7];
    const float* We2  = (const float*)d_in[8];
    const float* be2  = (const float*)d_in[9];
    const float* W2   = (const float*)d_in[10];
    const float* b2   = (const float*)d_in[11];
    const float* We3  = (const float*)d_in[12];
    const float* be3  = (const float*)d_in[13];
    const float* W3   = (const float*)d_in[14];
    const float* b3   = (const float*)d_in[15];
    const float* Wlin = (const float*)d_in[16];
    const float* blin = (const float*)d_in[17];
    float* out = (float*)d_out;

    const int* src = ei;
    const int* dst = ei + N_EDGESC;

    float *agg, *h0, *h1, *pool, *cnt;
    int *deg, *off, *cur, *bsum, *perm;
    cudaGetSymbolAddress((void**)&agg, g_agg);
    cudaGetSymbolAddress((void**)&h0, g_h0);
    cudaGetSymbolAddress((void**)&h1, g_h1);
    cudaGetSymbolAddress((void**)&pool, g_pool);
    cudaGetSymbolAddress((void**)&cnt, g_cnt);
    cudaGetSymbolAddress((void**)&deg, g_deg);
    cudaGetSymbolAddress((void**)&off, g_off);
    cudaGetSymbolAddress((void**)&cur, g_cur);
    cudaGetSymbolAddress((void**)&bsum, g_bsum);
    cudaGetSymbolAddress((void**)&perm, g_perm);

    cudaFuncSetAttribute(gemm128, cudaFuncAttributeMaxDynamicSharedMemorySize,
                         GEMM_SMEM);

    const int warp_blocks = (N_NODESC * 32 + 255) / 256;  // warp per node

    // ---- build CSR-by-destination (once; reused by all 3 layers) ----
    cudaMemsetAsync(deg, 0, N_NODESC * sizeof(int));
    hist_kernel<<<(N_EDGESC + 255) / 256, 256>>>(dst, deg);
    scan_local<<<SCAN_NB, SCAN_T>>>(deg, off, bsum);
    scan_sums<<<1, 32>>>(bsum);
    scan_add<<<SCAN_NB, SCAN_T>>>(off, bsum);
    cudaMemcpyAsync(cur, off, N_NODESC * sizeof(int), cudaMemcpyDeviceToDevice);
    fill_kernel<<<(N_EDGESC + 255) / 256, 256>>>(dst, cur, perm);

    // ---- layer 1 (in=7) ----
    gather7<<<warp_blocks, 256>>>(x, src, ea, perm, off, We1, be1, agg);
    gemm7<<<(N_NODESC + GM1 - 1) / GM1, 128>>>(agg, x, W1, b1, h0);

    // ---- layer 2 ----
    gather128<<<warp_blocks, 256>>>(h0, src, ea, perm, off, We2, be2, agg);
    gemm128<<<296, 256, GEMM_SMEM>>>(agg, h0, W2, b2, h1);

    // ---- layer 3 ----
    gather128<<<warp_blocks, 256>>>(h1, src, ea, perm, off, We3, be3, agg);
    gemm128<<<296, 256, GEMM_SMEM>>>(agg, h1, W3, b3, h0);

    // ---- mean pool + classifier ----
    cudaMemsetAsync(pool, 0, NGRAPHS * HID * sizeof(float));
    cudaMemsetAsync(cnt, 0, NGRAPHS * sizeof(float));
    pool_kernel<<<(N_NODESC + POOL_CHUNK - 1) / POOL_CHUNK, 128>>>(h0, batch, pool, cnt);
    final_kernel<<<1, 64>>>(pool, cnt, Wlin, blin, out);
}

// round 9
// speedup vs baseline: 1.5583x; 1.0420x over previous
#include <cuda_runtime.h>
#include <cstddef>

#define N_NODESC 100000
#define N_EDGESC 1600000
#define NFEAT 7
#define HID 128
#define NCLASS 5
#define NGRAPHS 8

// ---------------- scratch (device globals; no allocation allowed) ----------
__device__ __align__(16) float g_agg[N_NODESC * HID];
__device__ __align__(16) float g_h0[N_NODESC * HID];
__device__ __align__(16) float g_h1[N_NODESC * HID];
__device__ float g_pool[NGRAPHS * HID];
__device__ float g_cnt[NGRAPHS];
// CSR-by-destination scratch
__device__ int g_deg[N_NODESC];
__device__ int g_off[N_NODESC + 1];
__device__ int g_cur[N_NODESC];
__device__ int g_bsum[128];
__device__ int g_perm[N_EDGESC];
// edge data pre-permuted into CSR order (kills one level of indirection)
__device__ int g_srcs[N_EDGESC];
__device__ float g_eas[N_EDGESC];

// ================= CSR build ===============================================
__global__ void hist_kernel(const int* __restrict__ dst, int* __restrict__ deg) {
    int e = blockIdx.x * blockDim.x + threadIdx.x;
    if (e < N_EDGESC) atomicAdd(&deg[dst[e]], 1);
}

#define SCAN_T 256
#define SCAN_E 1024
#define SCAN_NB ((N_NODESC + SCAN_E - 1) / SCAN_E)   // 98

__global__ void scan_local(const int* __restrict__ deg, int* __restrict__ off,
                           int* __restrict__ bsum) {
    __shared__ int tsum[SCAN_T];
    int b = blockIdx.x, t = threadIdx.x;
    int base = b * SCAN_E + t * 4;
    int v[4], ex[4];
    int run = 0;
#pragma unroll
    for (int j = 0; j < 4; j++) {
        int idx = base + j;
        v[j] = (idx < N_NODESC) ? deg[idx] : 0;
        ex[j] = run;
        run += v[j];
    }
    tsum[t] = run;
    __syncthreads();
    for (int ofs = 1; ofs < SCAN_T; ofs <<= 1) {
        int val = (t >= ofs) ? tsum[t - ofs] : 0;
        __syncthreads();
        tsum[t] += val;
        __syncthreads();
    }
    int texc = tsum[t] - run;
#pragma unroll
    for (int j = 0; j < 4; j++) {
        int idx = base + j;
        if (idx < N_NODESC) off[idx] = texc + ex[j];
    }
    if (t == SCAN_T - 1) bsum[b] = tsum[t];
}

__global__ void scan_sums(int* __restrict__ bsum) {
    if (threadIdx.x == 0) {
        int run = 0;
        for (int b = 0; b < SCAN_NB; b++) {
            int t = bsum[b];
            bsum[b] = run;
            run += t;
        }
    }
}

__global__ void scan_add(int* __restrict__ off, const int* __restrict__ bsum) {
    int b = blockIdx.x, t = threadIdx.x;
    int add = bsum[b];
    int base = b * SCAN_E + t * 4;
#pragma unroll
    for (int j = 0; j < 4; j++) {
        int idx = base + j;
        if (idx < N_NODESC) off[idx] += add;
    }
    if (b == 0 && t == 0) off[N_NODESC] = N_EDGESC;
}

__global__ void fill_kernel(const int* __restrict__ dst, int* __restrict__ cur,
                            int* __restrict__ perm) {
    int e = blockIdx.x * blockDim.x + threadIdx.x;
    if (e < N_EDGESC) {
        int p = atomicAdd(&cur[dst[e]], 1);
        perm[p] = e;
    }
}

// pre-permute src/ea into CSR order: srcs[i] = src[perm[i]], eas[i] = ea[perm[i]]
__global__ void permute_edges(const int* __restrict__ perm,
                              const int* __restrict__ src,
                              const float* __restrict__ ea,
                              int* __restrict__ srcs,
                              float* __restrict__ eas) {
    int i = blockIdx.x * blockDim.x + threadIdx.x;
    if (i < N_EDGESC) {
        int e = perm[i];
        srcs[i] = __ldg(&src[e]);
        eas[i] = __ldg(&ea[e]);
    }
}

// ================= layer 1: in = 7, gather by destination ==================
__global__ void __launch_bounds__(256)
gather7(const float* __restrict__ x, const int* __restrict__ srcs,
        const float* __restrict__ eas, const int* __restrict__ off,
        const float* __restrict__ We, const float* __restrict__ be,
        float* __restrict__ agg7) {
    int n = (blockIdx.x * blockDim.x + threadIdx.x) >> 5;
    int lane = threadIdx.x & 31;
    if (n >= N_NODESC) return;
    float w[NFEAT], bb[NFEAT];
#pragma unroll
    for (int j = 0; j < NFEAT; j++) { w[j] = __ldg(&We[j]); bb[j] = __ldg(&be[j]); }
    int i0 = __ldg(&off[n]), i1 = __ldg(&off[n + 1]);
    float acc[NFEAT];
#pragma unroll
    for (int j = 0; j < NFEAT; j++) acc[j] = 0.0f;
    for (int i = i0 + lane; i < i1; i += 32) {
        int s = __ldg(&srcs[i]);
        float a = __ldg(&eas[i]);
#pragma unroll
        for (int j = 0; j < NFEAT; j++)
            acc[j] += fmaxf(fmaf(a, w[j], bb[j]) + __ldg(&x[s * NFEAT + j]), 0.0f);
    }
#pragma unroll
    for (int o = 16; o > 0; o >>= 1)
#pragma unroll
        for (int j = 0; j < NFEAT; j++)
            acc[j] += __shfl_down_sync(0xffffffffu, acc[j], o);
    if (lane == 0) {
#pragma unroll
        for (int j = 0; j < NFEAT; j++) agg7[n * NFEAT + j] = acc[j];
    }
}

// ---------------- layer 1 gemm: [N,7] @ [7,128], relu ---------------------
#define GM1 32
__global__ void gemm7(const float* __restrict__ agg, const float* __restrict__ x,
                      const float* __restrict__ W, const float* __restrict__ b,
                      float* __restrict__ out) {
    __shared__ float Ws[NFEAT * HID];
    __shared__ float bs[HID];
    int j = threadIdx.x;  // 128 threads
#pragma unroll
    for (int k = 0; k < NFEAT; k++) Ws[k * HID + j] = W[k * HID + j];
    bs[j] = b[j];
    __syncthreads();
    int row0 = blockIdx.x * GM1;
    for (int r = 0; r < GM1; r++) {
        int row = row0 + r;
        if (row >= N_NODESC) return;
        float a[NFEAT];
#pragma unroll
        for (int k = 0; k < NFEAT; k++)
            a[k] = __ldg(&agg[row * NFEAT + k]) + __ldg(&x[row * NFEAT + k]);
        float acc = bs[j];
#pragma unroll
        for (int k = 0; k < NFEAT; k++) acc = fmaf(a[k], Ws[k * HID + j], acc);
        out[(size_t)row * HID + j] = fmaxf(acc, 0.0f);
    }
}

// ================= layers 2,3: gather-aggregate, warp per node =============
// 4-edge software pipeline; srcs/eas already in CSR order (2-level dep chain).
__global__ void __launch_bounds__(256)
gather128(const float* __restrict__ hin, const int* __restrict__ srcs,
          const float* __restrict__ eas, const int* __restrict__ off,
          const float* __restrict__ We, const float* __restrict__ be,
          float* __restrict__ agg) {
    int n = (blockIdx.x * blockDim.x + threadIdx.x) >> 5;
    int lane = threadIdx.x & 31;
    if (n >= N_NODESC) return;
    float4 w = __ldg(&((const float4*)We)[lane]);
    float4 bb = __ldg(&((const float4*)be)[lane]);
    int i = __ldg(&off[n]);
    int end = __ldg(&off[n + 1]);
    const float4* h4 = (const float4*)hin;
    float4 acc = make_float4(0.f, 0.f, 0.f, 0.f);

    for (; i + 4 <= end; i += 4) {
        int s0 = __ldg(&srcs[i]);
        int s1 = __ldg(&srcs[i + 1]);
        int s2 = __ldg(&srcs[i + 2]);
        int s3 = __ldg(&srcs[i + 3]);
        float a0 = __ldg(&eas[i]);
        float a1 = __ldg(&eas[i + 1]);
        float a2 = __ldg(&eas[i + 2]);
        float a3 = __ldg(&eas[i + 3]);
        float4 v0 = h4[(size_t)s0 * (HID / 4) + lane];
        float4 v1 = h4[(size_t)s1 * (HID / 4) + lane];
        float4 v2 = h4[(size_t)s2 * (HID / 4) + lane];
        float4 v3 = h4[(size_t)s3 * (HID / 4) + lane];
        acc.x += fmaxf(fmaf(a0, w.x, bb.x) + v0.x, 0.f);
        acc.y += fmaxf(fmaf(a0, w.y, bb.y) + v0.y, 0.f);
        acc.z += fmaxf(fmaf(a0, w.z, bb.z) + v0.z, 0.f);
        acc.w += fmaxf(fmaf(a0, w.w, bb.w) + v0.w, 0.f);
        acc.x += fmaxf(fmaf(a1, w.x, bb.x) + v1.x, 0.f);
        acc.y += fmaxf(fmaf(a1, w.y, bb.y) + v1.y, 0.f);
        acc.z += fmaxf(fmaf(a1, w.z, bb.z) + v1.z, 0.f);
        acc.w += fmaxf(fmaf(a1, w.w, bb.w) + v1.w, 0.f);
        acc.x += fmaxf(fmaf(a2, w.x, bb.x) + v2.x, 0.f);
        acc.y += fmaxf(fmaf(a2, w.y, bb.y) + v2.y, 0.f);
        acc.z += fmaxf(fmaf(a2, w.z, bb.z) + v2.z, 0.f);
        acc.w += fmaxf(fmaf(a2, w.w, bb.w) + v2.w, 0.f);
        acc.x += fmaxf(fmaf(a3, w.x, bb.x) + v3.x, 0.f);
        acc.y += fmaxf(fmaf(a3, w.y, bb.y) + v3.y, 0.f);
        acc.z += fmaxf(fmaf(a3, w.z, bb.z) + v3.z, 0.f);
        acc.w += fmaxf(fmaf(a3, w.w, bb.w) + v3.w, 0.f);
    }
    for (; i < end; i++) {
        int s0 = __ldg(&srcs[i]);
        float a0 = __ldg(&eas[i]);
        float4 v0 = h4[(size_t)s0 * (HID / 4) + lane];
        acc.x += fmaxf(fmaf(a0, w.x, bb.x) + v0.x, 0.f);
        acc.y += fmaxf(fmaf(a0, w.y, bb.y) + v0.y, 0.f);
        acc.z += fmaxf(fmaf(a0, w.z, bb.z) + v0.z, 0.f);
        acc.w += fmaxf(fmaf(a0, w.w, bb.w) + v0.w, 0.f);
    }
    ((float4*)agg)[(size_t)n * (HID / 4) + lane] = acc;
}

// ---------------- layers 2,3 gemm: relu((agg + xin) @ W + b) --------------
#define BM 64
#define GEMM_SMEM ((HID * HID + BM * HID + HID) * 4)
__global__ void __launch_bounds__(256, 2)
gemm128(const float* __restrict__ agg, const float* __restrict__ xin,
        const float* __restrict__ W, const float* __restrict__ b,
        float* __restrict__ out) {
    extern __shared__ float smem[];
    float* Ws = smem;                 // [128][128]
    float* As = smem + HID * HID;     // [64][128]
    float* bs = As + BM * HID;        // [128]

    {
        const float4* Wg = (const float4*)W;
        float4* Ws4 = (float4*)Ws;
        for (int i = threadIdx.x; i < HID * (HID / 4); i += 256) Ws4[i] = Wg[i];
        if (threadIdx.x < HID) bs[threadIdx.x] = b[threadIdx.x];
    }
    __syncthreads();

    int cg = threadIdx.x & 31;
    int rg = threadIdx.x >> 5;
    int j0 = cg * 4;
    int r0 = rg * 8;

    int ntiles = (N_NODESC + BM - 1) / BM;
    for (int tile = blockIdx.x; tile < ntiles; tile += gridDim.x) {
        int row0 = tile * BM;
        {
            float4* As4 = (float4*)As;
            for (int i = threadIdx.x; i < BM * (HID / 4); i += 256) {
                int r = i >> 5;
                int kq = i & 31;
                int row = row0 + r;
                float4 v = make_float4(0.f, 0.f, 0.f, 0.f);
                if (row < N_NODESC) {
                    float4 ag = ((const float4*)(agg + (size_t)row * HID))[kq];
                    float4 xx = ((const float4*)(xin + (size_t)row * HID))[kq];
                    v = make_float4(ag.x + xx.x, ag.y + xx.y, ag.z + xx.z, ag.w + xx.w);
                }
                As4[i] = v;
            }
        }
        __syncthreads();

        float acc[8][4];
        {
            float4 bv = *(const float4*)&bs[j0];
#pragma unroll
            for (int i = 0; i < 8; i++) {
                acc[i][0] = bv.x; acc[i][1] = bv.y; acc[i][2] = bv.z; acc[i][3] = bv.w;
            }
        }

#pragma unroll 4
        for (int kk = 0; kk < HID; kk += 4) {
            float4 av[8];
#pragma unroll
            for (int i = 0; i < 8; i++)
                av[i] = *(const float4*)&As[(r0 + i) * HID + kk];
#pragma unroll
            for (int q = 0; q < 4; q++) {
                float4 wv = *(const float4*)&Ws[(kk + q) * HID + j0];
#pragma unroll
                for (int i = 0; i < 8; i++) {
                    float aval = (q == 0) ? av[i].x : (q == 1) ? av[i].y
                               : (q == 2) ? av[i].z : av[i].w;
                    acc[i][0] = fmaf(aval, wv.x, acc[i][0]);
                    acc[i][1] = fmaf(aval, wv.y, acc[i][1]);
                    acc[i][2] = fmaf(aval, wv.z, acc[i][2]);
                    acc[i][3] = fmaf(aval, wv.w, acc[i][3]);
                }
            }
        }

#pragma unroll
        for (int i = 0; i < 8; i++) {
            int row = row0 + r0 + i;
            if (row < N_NODESC) {
                float4 o;
                o.x = fmaxf(acc[i][0], 0.0f);
                o.y = fmaxf(acc[i][1], 0.0f);
                o.z = fmaxf(acc[i][2], 0.0f);
                o.w = fmaxf(acc[i][3], 0.0f);
                *(float4*)&out[(size_t)row * HID + j0] = o;
            }
        }
        __syncthreads();
    }
}

// ---------------- mean pool: segment sums over sorted batch ---------------
#define POOL_CHUNK 512
__global__ void pool_kernel(const float* __restrict__ h,
                            const int* __restrict__ batch,
                            float* __restrict__ pool,
                            float* __restrict__ cnt) {
    int j = threadIdx.x;  // 128
    int start = blockIdx.x * POOL_CHUNK;
    if (start >= N_NODESC) return;
    int end = start + POOL_CHUNK;
    if (end > N_NODESC) end = N_NODESC;
    int cur = __ldg(&batch[start]);
    float acc = 0.0f, c = 0.0f;
    for (int i = start; i < end; i++) {
        int bg = __ldg(&batch[i]);
        if (bg != cur) {
            atomicAdd(&pool[cur * HID + j], acc);
            if (j == 0) atomicAdd(&cnt[cur], c);
            acc = 0.0f; c = 0.0f; cur = bg;
        }
        acc += h[(size_t)i * HID + j];
        c += 1.0f;
    }
    atomicAdd(&pool[cur * HID + j], acc);
    if (j == 0) atomicAdd(&cnt[cur], c);
}

// ---------------- final: (pool/cnt) @ Wlin + blin, 8x5 out ----------------
__global__ void final_kernel(const float* __restrict__ pool,
                             const float* __restrict__ cnt,
                             const float* __restrict__ Wlin,
                             const float* __restrict__ blin,
                             float* __restrict__ out) {
    int t = threadIdx.x;
    if (t >= NGRAPHS * NCLASS) return;
    int g = t / NCLASS, c = t % NCLASS;
    float inv = 1.0f / fmaxf(cnt[g], 1.0f);
    float acc = blin[c];
#pragma unroll 8
    for (int k = 0; k < HID; k++)
        acc = fmaf(pool[g * HID + k] * inv, Wlin[k * NCLASS + c], acc);
    out[t] = acc;
}

// ---------------- launch ---------------------------------------------------
extern "C" void kernel_launch(void* const* d_in, const int* in_sizes, int n_in,
                              void* d_out, int out_size) {
    const float* x    = (const float*)d_in[0];
    const int*   ei   = (const int*)d_in[1];
    const float* ea   = (const float*)d_in[2];
    const int*   batch= (const int*)d_in[3];
    const float* We1  = (const float*)d_in[4];
    const float* be1  = (const float*)d_in[5];
    const float* W1   = (const float*)d_in[6];
    const float* b1   = (const float*)d_in[7];
    const float* We2  = (const float*)d_in[8];
    const float* be2  = (const float*)d_in[9];
    const float* W2   = (const float*)d_in[10];
    const float* b2   = (const float*)d_in[11];
    const float* We3  = (const float*)d_in[12];
    const float* be3  = (const float*)d_in[13];
    const float* W3   = (const float*)d_in[14];
    const float* b3   = (const float*)d_in[15];
    const float* Wlin = (const float*)d_in[16];
    const float* blin = (const float*)d_in[17];
    float* out = (float*)d_out;

    const int* src = ei;
    const int* dst = ei + N_EDGESC;

    float *agg, *h0, *h1, *pool, *cnt, *eas;
    int *deg, *off, *cur, *bsum, *perm, *srcs;
    cudaGetSymbolAddress((void**)&agg, g_agg);
    cudaGetSymbolAddress((void**)&h0, g_h0);
    cudaGetSymbolAddress((void**)&h1, g_h1);
    cudaGetSymbolAddress((void**)&pool, g_pool);
    cudaGetSymbolAddress((void**)&cnt, g_cnt);
    cudaGetSymbolAddress((void**)&deg, g_deg);
    cudaGetSymbolAddress((void**)&off, g_off);
    cudaGetSymbolAddress((void**)&cur, g_cur);
    cudaGetSymbolAddress((void**)&bsum, g_bsum);
    cudaGetSymbolAddress((void**)&perm, g_perm);
    cudaGetSymbolAddress((void**)&srcs, g_srcs);
    cudaGetSymbolAddress((void**)&eas, g_eas);

    cudaFuncSetAttribute(gemm128, cudaFuncAttributeMaxDynamicSharedMemorySize,
                         GEMM_SMEM);

    const int warp_blocks = (N_NODESC * 32 + 255) / 256;  // warp per node

    // ---- build CSR-by-destination + permuted edge data (reused 3x) ----
    cudaMemsetAsync(deg, 0, N_NODESC * sizeof(int));
    hist_kernel<<<(N_EDGESC + 255) / 256, 256>>>(dst, deg);
    scan_local<<<SCAN_NB, SCAN_T>>>(deg, off, bsum);
    scan_sums<<<1, 32>>>(bsum);
    scan_add<<<SCAN_NB, SCAN_T>>>(off, bsum);
    cudaMemcpyAsync(cur, off, N_NODESC * sizeof(int), cudaMemcpyDeviceToDevice);
    fill_kernel<<<(N_EDGESC + 255) / 256, 256>>>(dst, cur, perm);
    permute_edges<<<(N_EDGESC + 255) / 256, 256>>>(perm, src, ea, srcs, eas);

    // ---- layer 1 (in=7) ----
    gather7<<<warp_blocks, 256>>>(x, srcs, eas, off, We1, be1, agg);
    gemm7<<<(N_NODESC + GM1 - 1) / GM1, 128>>>(agg, x, W1, b1, h0);

    // ---- layer 2 ----
    gather128<<<warp_blocks, 256>>>(h0, srcs, eas, off, We2, be2, agg);
    gemm128<<<296, 256, GEMM_SMEM>>>(agg, h0, W2, b2, h1);

    // ---- layer 3 ----
    gather128<<<warp_blocks, 256>>>(h1, srcs, eas, off, We3, be3, agg);
    gemm128<<<296, 256, GEMM_SMEM>>>(agg, h1, W3, b3, h0);

    // ---- mean pool + classifier ----
    cudaMemsetAsync(pool, 0, NGRAPHS * HID * sizeof(float));
    cudaMemsetAsync(cnt, 0, NGRAPHS * sizeof(float));
    pool_kernel<<<(N_NODESC + POOL_CHUNK - 1) / POOL_CHUNK, 128>>>(h0, batch, pool, cnt);
    final_kernel<<<1, 64>>>(pool, cnt, Wlin, blin, out);
}